// round 2
// baseline (speedup 1.0000x reference)
#include <cuda_runtime.h>
#include <cuda_bf16.h>
#include <math.h>

// Problem constants
#define BB   2
#define TT   2048
#define CC   1024
#define HH   16
#define DD   64
#define MTOT (BB*TT)          // 4096
#define QKVN (3*CC)           // 3072

// ---------------- scratch (device globals; no allocs allowed) ----------------
__device__ float g_qkv[(size_t)MTOT * QKVN];      // 4096 x 3072
__device__ float g_q[(size_t)BB*HH*TT*DD];        // [B*H, T, D]
__device__ float g_k[(size_t)BB*HH*TT*DD];
__device__ float g_v[(size_t)BB*HH*TT*DD];
__device__ float g_att[(size_t)MTOT * CC];        // [B,T,C] attention output

// ---------------- generic fp32 tiled GEMM: C = A[M,K] @ B[K,N] (+bias) -------
#define BM 128
#define BN 128
#define BKS 16
#define TM 8
#define TN 8

__device__ __forceinline__ void sgemm_body(
    const float* __restrict__ A, const float* __restrict__ B,
    const float* __restrict__ bias, float* __restrict__ C,
    int M, int N, int K)
{
    __shared__ float As[BKS][BM];
    __shared__ float Bs[BKS][BN];

    const int tid = threadIdx.x;
    const int brow = blockIdx.y;
    const int bcol = blockIdx.x;

    const float* Ab = A + (size_t)brow * BM * K;
    const float* Bb = B + (size_t)bcol * BN;

    const int aRow = tid >> 2;           // 0..63  (two passes cover 128 rows)
    const int aCol = (tid & 3) * 4;      // 0,4,8,12
    const int bRow = tid >> 5;           // 0..7   (two passes cover 16 rows)
    const int bCol = (tid & 31) * 4;     // 0..124
    const int tRow = (tid >> 4) * TM;    // 0..120
    const int tCol = (tid & 15) * TN;    // 0..120

    float acc[TM][TN] = {};

    for (int k0 = 0; k0 < K; k0 += BKS) {
#pragma unroll
        for (int i = 0; i < 2; i++) {
            int r = aRow + i * 64;
            float4 va = *(const float4*)(Ab + (size_t)r * K + k0 + aCol);
            As[aCol + 0][r] = va.x;
            As[aCol + 1][r] = va.y;
            As[aCol + 2][r] = va.z;
            As[aCol + 3][r] = va.w;
        }
#pragma unroll
        for (int i = 0; i < 2; i++) {
            int r = bRow + i * 8;
            float4 vb = *(const float4*)(Bb + (size_t)(k0 + r) * N + bCol);
            *(float4*)&Bs[r][bCol] = vb;
        }
        __syncthreads();

#pragma unroll
        for (int kk = 0; kk < BKS; kk++) {
            float ra[TM], rb[TN];
            *(float4*)&ra[0] = *(const float4*)&As[kk][tRow];
            *(float4*)&ra[4] = *(const float4*)&As[kk][tRow + 4];
            *(float4*)&rb[0] = *(const float4*)&Bs[kk][tCol];
            *(float4*)&rb[4] = *(const float4*)&Bs[kk][tCol + 4];
#pragma unroll
            for (int i = 0; i < TM; i++)
#pragma unroll
                for (int j = 0; j < TN; j++)
                    acc[i][j] += ra[i] * rb[j];
        }
        __syncthreads();
    }

#pragma unroll
    for (int i = 0; i < TM; i++) {
#pragma unroll
        for (int j = 0; j < TN; j += 4) {
            int col = bcol * BN + tCol + j;
            float4 v;
            v.x = acc[i][j + 0];
            v.y = acc[i][j + 1];
            v.z = acc[i][j + 2];
            v.w = acc[i][j + 3];
            if (bias) {
                v.x += bias[col + 0];
                v.y += bias[col + 1];
                v.z += bias[col + 2];
                v.w += bias[col + 3];
            }
            *(float4*)(C + (size_t)(brow * BM + tRow + i) * N + col) = v;
        }
    }
}

__global__ __launch_bounds__(256)
void qkv_gemm_kernel(const float* __restrict__ x, const float* __restrict__ Wqkv)
{
    sgemm_body(x, Wqkv, nullptr, g_qkv, MTOT, QKVN, CC);
}

__global__ __launch_bounds__(256)
void oproj_gemm_kernel(const float* __restrict__ Wo, const float* __restrict__ bo,
                       float* __restrict__ out)
{
    sgemm_body(g_att, Wo, bo, out, MTOT, CC, CC);
}

// ---------------- RoPE + scatter to [B*H, T, D] ------------------------------
// pair index space: [MTOT rows] x [3 sel] x [16 heads] x [32 pairs] = 6291456
__global__ void rope_scatter_kernel()
{
    int idx = blockIdx.x * blockDim.x + threadIdx.x;
    const int TOT = MTOT * 3 * HH * (DD / 2);
    if (idx >= TOT) return;

    int row = idx / 1536;            // b*T + t
    int c0  = idx % 1536;
    int sel = c0 / 512;              // 0=q 1=k 2=v
    int h   = (c0 % 512) / 32;
    int p   = c0 % 32;               // pair index (d = 2p, 2p+1)
    int t   = row % TT;
    int b   = row / TT;

    size_t src = (size_t)row * QKVN + sel * CC + h * DD + 2 * p;
    float x0 = g_qkv[src];
    float x1 = g_qkv[src + 1];

    float* dst = (sel == 0) ? g_q : (sel == 1) ? g_k : g_v;
    size_t o = ((size_t)(b * HH + h) * TT + t) * DD + 2 * p;

    if (sel < 2) {
        // 10000^(-p/32) = exp(-p * ln(10000)/32); exact arg, __expf err ~2e-6
        const float LN1E4_OVER_32 = 0.28782313662425572f;
        float inv_freq = __expf(-(float)p * LN1E4_OVER_32);
        float ang = (float)t * inv_freq;
        float s, c;
        sincosf(ang, &s, &c);
        dst[o]     = x0 * c - x1 * s;
        dst[o + 1] = x1 * c + x0 * s;
    } else {
        dst[o]     = x0;
        dst[o + 1] = x1;
    }
}

// ---------------- flash attention (fp32, causal, online softmax) --------------
#define BQ 128      // queries per CTA (1 per thread)
#define BKT 32      // key tile

__global__ __launch_bounds__(BQ)
void attn_kernel()
{
    __shared__ float Ks[BKT][DD];
    __shared__ float Vs[BKT][DD];

    const int bh  = blockIdx.y;          // 0..31  (b*16 + h)
    const int q0  = blockIdx.x * BQ;
    const int tid = threadIdx.x;
    const int qi  = q0 + tid;

    const float* Qb = g_q + (size_t)bh * TT * DD;
    const float* Kb = g_k + (size_t)bh * TT * DD;
    const float* Vb = g_v + (size_t)bh * TT * DD;

    const float scale = 0.125f;          // D^-0.5, D=64

    float q[DD];
#pragma unroll
    for (int d = 0; d < DD; d += 4) {
        float4 v = *(const float4*)(Qb + (size_t)qi * DD + d);
        q[d + 0] = v.x * scale;
        q[d + 1] = v.y * scale;
        q[d + 2] = v.z * scale;
        q[d + 3] = v.w * scale;
    }

    float m = -INFINITY;
    float l = 0.0f;
    float acc[DD] = {};

    for (int j0 = 0; j0 < q0 + BQ; j0 += BKT) {
        // cooperative tile load: 32x64 floats = 512 float4 per tile
#pragma unroll
        for (int i = 0; i < (BKT * DD / 4) / BQ; i++) {
            int e = tid + i * BQ;
            ((float4*)&Ks[0][0])[e] = ((const float4*)(Kb + (size_t)j0 * DD))[e];
            ((float4*)&Vs[0][0])[e] = ((const float4*)(Vb + (size_t)j0 * DD))[e];
        }
        __syncthreads();

        float s[BKT];
#pragma unroll
        for (int j = 0; j < BKT; j++) {
            float sum = 0.0f;
#pragma unroll
            for (int d = 0; d < DD; d += 4) {
                float4 kv = *(const float4*)&Ks[j][d];
                sum += q[d + 0] * kv.x + q[d + 1] * kv.y
                     + q[d + 2] * kv.z + q[d + 3] * kv.w;
            }
            s[j] = sum;
        }

        if (j0 + BKT - 1 > q0) {         // tile may cross the diagonal
#pragma unroll
            for (int j = 0; j < BKT; j++)
                if (j0 + j > qi) s[j] = -INFINITY;
        }

        float mt = m;
#pragma unroll
        for (int j = 0; j < BKT; j++) mt = fmaxf(mt, s[j]);

        float resc = __expf(m - mt);     // 0 on first tile (m=-inf, mt finite)
        l *= resc;
#pragma unroll
        for (int d = 0; d < DD; d++) acc[d] *= resc;
        m = mt;

#pragma unroll
        for (int j = 0; j < BKT; j++) {
            float p = __expf(s[j] - m);
            l += p;
#pragma unroll
            for (int d = 0; d < DD; d += 4) {
                float4 vv = *(const float4*)&Vs[j][d];
                acc[d + 0] += p * vv.x;
                acc[d + 1] += p * vv.y;
                acc[d + 2] += p * vv.z;
                acc[d + 3] += p * vv.w;
            }
        }
        __syncthreads();
    }

    // write to [B, T, C] with head-interleave undone: out[b, t, h*64+d]
    const int b = bh >> 4;
    const int h = bh & 15;
    const float inv = 1.0f / l;
    float* op = g_att + ((size_t)(b * TT + qi)) * CC + h * DD;
#pragma unroll
    for (int d = 0; d < DD; d += 4) {
        float4 v;
        v.x = acc[d + 0] * inv;
        v.y = acc[d + 1] * inv;
        v.z = acc[d + 2] * inv;
        v.w = acc[d + 3] * inv;
        *(float4*)(op + d) = v;
    }
}

// ---------------- launch ------------------------------------------------------
extern "C" void kernel_launch(void* const* d_in, const int* in_sizes, int n_in,
                              void* d_out, int out_size)
{
    const float* x    = (const float*)d_in[0];
    const float* Wqkv = (const float*)d_in[1];
    const float* Wo   = (const float*)d_in[2];
    const float* bo   = (const float*)d_in[3];
    float* out = (float*)d_out;

    (void)in_sizes; (void)n_in; (void)out_size;

    // 1) QKV projection: [4096,1024] @ [1024,3072]
    {
        dim3 grid(QKVN / BN, MTOT / BM);   // (24, 32)
        qkv_gemm_kernel<<<grid, 256>>>(x, Wqkv);
    }

    // 2) RoPE + scatter to [B*H, T, D]
    {
        int tot = MTOT * 3 * HH * (DD / 2);   // 6291456
        rope_scatter_kernel<<<(tot + 255) / 256, 256>>>();
    }

    // 3) causal flash attention
    {
        dim3 grid(TT / BQ, BB * HH);       // (16, 32)
        attn_kernel<<<grid, BQ>>>();
    }

    // 4) output projection + bias: [4096,1024] @ [1024,1024] + bo
    {
        dim3 grid(CC / BN, MTOT / BM);     // (8, 32)
        oproj_gemm_kernel<<<grid, 256>>>(Wo, bo, out);
    }
}

// round 3
// speedup vs baseline: 1.1506x; 1.1506x over previous
#include <cuda_runtime.h>
#include <cuda_bf16.h>
#include <math.h>

// Problem constants
#define BB   2
#define TT   2048
#define CC   1024
#define HH   16
#define DD   64
#define MTOT (BB*TT)          // 4096
#define QKVN (3*CC)           // 3072

// ---------------- scratch (device globals; no allocs allowed) ----------------
__device__ float g_qkv[(size_t)MTOT * QKVN];      // 4096 x 3072
__device__ float g_q[(size_t)BB*HH*TT*DD];        // [B*H, T, D]
__device__ float g_k[(size_t)BB*HH*TT*DD];
__device__ float g_v[(size_t)BB*HH*TT*DD];
__device__ float g_att[(size_t)MTOT * CC];        // [B,T,C] attention output

// ---------------- fp32 tiled GEMM, double-buffered: C = A@B (+bias) ----------
#define BM 128
#define BN 128
#define BKS 16
#define TM 8
#define TN 8

__device__ __forceinline__ void sgemm_body(
    const float* __restrict__ A, const float* __restrict__ B,
    const float* __restrict__ bias, float* __restrict__ C,
    int M, int N, int K)
{
    __shared__ float As[2][BKS][BM];
    __shared__ float Bs[2][BKS][BN];

    const int tid = threadIdx.x;
    const int brow = blockIdx.y;
    const int bcol = blockIdx.x;

    const float* Ab = A + (size_t)brow * BM * K;
    const float* Bb = B + (size_t)bcol * BN;

    const int aRow = tid >> 2;           // 0..63  (two passes cover 128 rows)
    const int aCol = (tid & 3) * 4;      // 0,4,8,12
    const int bRow = tid >> 5;           // 0..7   (two passes cover 16 rows)
    const int bCol = (tid & 31) * 4;     // 0..124
    const int tRow = (tid >> 4) * TM;    // 0..120
    const int tCol = (tid & 15) * TN;    // 0..120

    float4 va0, va1, vb0, vb1;

    // prologue: k-tile 0 -> buffer 0
    va0 = *(const float4*)(Ab + (size_t)aRow * K + aCol);
    va1 = *(const float4*)(Ab + (size_t)(aRow + 64) * K + aCol);
    vb0 = *(const float4*)(Bb + (size_t)bRow * N + bCol);
    vb1 = *(const float4*)(Bb + (size_t)(bRow + 8) * N + bCol);
    As[0][aCol + 0][aRow] = va0.x;  As[0][aCol + 1][aRow] = va0.y;
    As[0][aCol + 2][aRow] = va0.z;  As[0][aCol + 3][aRow] = va0.w;
    As[0][aCol + 0][aRow + 64] = va1.x;  As[0][aCol + 1][aRow + 64] = va1.y;
    As[0][aCol + 2][aRow + 64] = va1.z;  As[0][aCol + 3][aRow + 64] = va1.w;
    *(float4*)&Bs[0][bRow][bCol] = vb0;
    *(float4*)&Bs[0][bRow + 8][bCol] = vb1;
    __syncthreads();

    float acc[TM][TN] = {};
    int cur = 0;

    for (int k0 = 0; k0 < K; k0 += BKS) {
        const bool more = (k0 + BKS) < K;
        if (more) {
            va0 = *(const float4*)(Ab + (size_t)aRow * K + k0 + BKS + aCol);
            va1 = *(const float4*)(Ab + (size_t)(aRow + 64) * K + k0 + BKS + aCol);
            vb0 = *(const float4*)(Bb + (size_t)(k0 + BKS + bRow) * N + bCol);
            vb1 = *(const float4*)(Bb + (size_t)(k0 + BKS + bRow + 8) * N + bCol);
        }

        const float (*Asc)[BM] = As[cur];
        const float (*Bsc)[BN] = Bs[cur];
#pragma unroll
        for (int kk = 0; kk < BKS; kk++) {
            float ra[TM], rb[TN];
            *(float4*)&ra[0] = *(const float4*)&Asc[kk][tRow];
            *(float4*)&ra[4] = *(const float4*)&Asc[kk][tRow + 4];
            *(float4*)&rb[0] = *(const float4*)&Bsc[kk][tCol];
            *(float4*)&rb[4] = *(const float4*)&Bsc[kk][tCol + 4];
#pragma unroll
            for (int i = 0; i < TM; i++)
#pragma unroll
                for (int j = 0; j < TN; j++)
                    acc[i][j] += ra[i] * rb[j];
        }

        if (more) {
            const int nxt = cur ^ 1;
            As[nxt][aCol + 0][aRow] = va0.x;  As[nxt][aCol + 1][aRow] = va0.y;
            As[nxt][aCol + 2][aRow] = va0.z;  As[nxt][aCol + 3][aRow] = va0.w;
            As[nxt][aCol + 0][aRow + 64] = va1.x;  As[nxt][aCol + 1][aRow + 64] = va1.y;
            As[nxt][aCol + 2][aRow + 64] = va1.z;  As[nxt][aCol + 3][aRow + 64] = va1.w;
            *(float4*)&Bs[nxt][bRow][bCol] = vb0;
            *(float4*)&Bs[nxt][bRow + 8][bCol] = vb1;
        }
        __syncthreads();
        cur ^= 1;
    }

#pragma unroll
    for (int i = 0; i < TM; i++) {
#pragma unroll
        for (int j = 0; j < TN; j += 4) {
            int col = bcol * BN + tCol + j;
            float4 v;
            v.x = acc[i][j + 0];
            v.y = acc[i][j + 1];
            v.z = acc[i][j + 2];
            v.w = acc[i][j + 3];
            if (bias) {
                v.x += bias[col + 0];
                v.y += bias[col + 1];
                v.z += bias[col + 2];
                v.w += bias[col + 3];
            }
            *(float4*)(C + (size_t)(brow * BM + tRow + i) * N + col) = v;
        }
    }
}

__global__ __launch_bounds__(256)
void qkv_gemm_kernel(const float* __restrict__ x, const float* __restrict__ Wqkv)
{
    sgemm_body(x, Wqkv, nullptr, g_qkv, MTOT, QKVN, CC);
}

__global__ __launch_bounds__(256)
void oproj_gemm_kernel(const float* __restrict__ Wo, const float* __restrict__ bo,
                       float* __restrict__ out)
{
    sgemm_body(g_att, Wo, bo, out, MTOT, CC, CC);
}

// ---------------- RoPE + scatter to [B*H, T, D] ------------------------------
__global__ void rope_scatter_kernel()
{
    int idx = blockIdx.x * blockDim.x + threadIdx.x;
    const int TOT = MTOT * 3 * HH * (DD / 2);
    if (idx >= TOT) return;

    int row = idx / 1536;            // b*T + t
    int c0  = idx % 1536;
    int sel = c0 / 512;              // 0=q 1=k 2=v
    int h   = (c0 % 512) / 32;
    int p   = c0 % 32;               // pair index (d = 2p, 2p+1)
    int t   = row % TT;
    int b   = row / TT;

    size_t src = (size_t)row * QKVN + sel * CC + h * DD + 2 * p;
    float x0 = g_qkv[src];
    float x1 = g_qkv[src + 1];

    float* dst = (sel == 0) ? g_q : (sel == 1) ? g_k : g_v;
    size_t o = ((size_t)(b * HH + h) * TT + t) * DD + 2 * p;

    if (sel < 2) {
        const float LN1E4_OVER_32 = 0.28782313662425572f;
        float inv_freq = __expf(-(float)p * LN1E4_OVER_32);
        float ang = (float)t * inv_freq;
        float s, c;
        sincosf(ang, &s, &c);
        dst[o]     = x0 * c - x1 * s;
        dst[o + 1] = x1 * c + x0 * s;
    } else {
        dst[o]     = x0;
        dst[o + 1] = x1;
    }
}

// ---------------- flash attention (fp32, causal, online softmax) --------------
// 256 threads = 8 warps. Warp handles 16 queries; lane pair (L, L^16) splits
// the 64 head dims (32 each). Score = own-half dot + shfl_xor reduce.
#define AT_THREADS 256
#define AT_BQ 128        // queries per CTA
#define AT_BKT 64        // keys per SMEM tile
#define AT_CH 16         // keys per softmax chunk

__global__ __launch_bounds__(AT_THREADS)
void attn_kernel()
{
    __shared__ float Ks[AT_BKT][DD];
    __shared__ float Vs[AT_BKT][DD];

    const int bh   = blockIdx.y;             // b*16 + h
    const int q0   = blockIdx.x * AT_BQ;
    const int tid  = threadIdx.x;
    const int warp = tid >> 5;
    const int lane = tid & 31;
    const int qloc = lane & 15;              // query within warp
    const int dh   = lane >> 4;              // dim half: 0 or 1
    const int qi   = q0 + warp * 16 + qloc;
    const int dbase = dh * 32;

    const float* Qb = g_q + ((size_t)bh * TT + qi) * DD + dbase;
    const float* Kb = g_k + (size_t)bh * TT * DD;
    const float* Vb = g_v + (size_t)bh * TT * DD;

    float q[32];
#pragma unroll
    for (int d = 0; d < 32; d += 4) {
        float4 v = *(const float4*)(Qb + d);
        q[d + 0] = v.x * 0.125f;
        q[d + 1] = v.y * 0.125f;
        q[d + 2] = v.z * 0.125f;
        q[d + 3] = v.w * 0.125f;
    }

    float m = -INFINITY, l = 0.0f;
    float acc[32] = {};

    const int wqmax = q0 + warp * 16 + 15;   // warp's last query (uniform)
    const int kend  = q0 + AT_BQ;

    for (int j0 = 0; j0 < kend; j0 += AT_BKT) {
        // cooperative tile load: 64x64 floats each = 1024 float4 per tensor
#pragma unroll
        for (int i = 0; i < (AT_BKT * DD / 4) / AT_THREADS; i++) {   // 4 iters
            int e = tid + i * AT_THREADS;
            ((float4*)&Ks[0][0])[e] = ((const float4*)(Kb + (size_t)j0 * DD))[e];
            ((float4*)&Vs[0][0])[e] = ((const float4*)(Vb + (size_t)j0 * DD))[e];
        }
        __syncthreads();

        for (int c0 = 0; c0 < AT_BKT; c0 += AT_CH) {
            const int kbase = j0 + c0;
            if (kbase > wqmax) break;        // warp-uniform

            float s[AT_CH];
#pragma unroll
            for (int j = 0; j < AT_CH; j++) {
                const float* kr = &Ks[c0 + j][dbase];
                float ps0 = 0.f, ps1 = 0.f, ps2 = 0.f, ps3 = 0.f;
#pragma unroll
                for (int d = 0; d < 32; d += 16) {
                    float4 a = *(const float4*)(kr + d + 0);
                    float4 b = *(const float4*)(kr + d + 4);
                    float4 c = *(const float4*)(kr + d + 8);
                    float4 e = *(const float4*)(kr + d + 12);
                    ps0 += q[d + 0]*a.x + q[d + 1]*a.y + q[d + 2]*a.z + q[d + 3]*a.w;
                    ps1 += q[d + 4]*b.x + q[d + 5]*b.y + q[d + 6]*b.z + q[d + 7]*b.w;
                    ps2 += q[d + 8]*c.x + q[d + 9]*c.y + q[d +10]*c.z + q[d +11]*c.w;
                    ps3 += q[d +12]*e.x + q[d +13]*e.y + q[d +14]*e.z + q[d +15]*e.w;
                }
                float part = (ps0 + ps1) + (ps2 + ps3);
                float full = part + __shfl_xor_sync(0xffffffffu, part, 16);
                s[j] = (kbase + j > qi) ? -INFINITY : full;
            }

            float mt = m;
#pragma unroll
            for (int j = 0; j < AT_CH; j++) mt = fmaxf(mt, s[j]);

            if (mt > -INFINITY) {
                float r = __expf(m - mt);    // 0 on first live chunk (m=-inf)
                l *= r;
#pragma unroll
                for (int d = 0; d < 32; d++) acc[d] *= r;
                m = mt;

#pragma unroll
                for (int j = 0; j < AT_CH; j++) {
                    float p = __expf(s[j] - m);
                    l += p;
                    const float* vr = &Vs[c0 + j][dbase];
#pragma unroll
                    for (int d = 0; d < 32; d += 4) {
                        float4 vv = *(const float4*)(vr + d);
                        acc[d + 0] += p * vv.x;
                        acc[d + 1] += p * vv.y;
                        acc[d + 2] += p * vv.z;
                        acc[d + 3] += p * vv.w;
                    }
                }
            }
        }
        __syncthreads();
    }

    // write out[b, qi, h*64 + dbase + d]
    const int b = bh >> 4;
    const int h = bh & 15;
    const float inv = 1.0f / l;
    float* op = g_att + ((size_t)(b * TT + qi)) * CC + h * DD + dbase;
#pragma unroll
    for (int d = 0; d < 32; d += 4) {
        float4 v;
        v.x = acc[d + 0] * inv;
        v.y = acc[d + 1] * inv;
        v.z = acc[d + 2] * inv;
        v.w = acc[d + 3] * inv;
        *(float4*)(op + d) = v;
    }
}

// ---------------- launch ------------------------------------------------------
extern "C" void kernel_launch(void* const* d_in, const int* in_sizes, int n_in,
                              void* d_out, int out_size)
{
    const float* x    = (const float*)d_in[0];
    const float* Wqkv = (const float*)d_in[1];
    const float* Wo   = (const float*)d_in[2];
    const float* bo   = (const float*)d_in[3];
    float* out = (float*)d_out;

    (void)in_sizes; (void)n_in; (void)out_size;

    // 1) QKV projection: [4096,1024] @ [1024,3072]
    {
        dim3 grid(QKVN / BN, MTOT / BM);   // (24, 32)
        qkv_gemm_kernel<<<grid, 256>>>(x, Wqkv);
    }

    // 2) RoPE + scatter to [B*H, T, D]
    {
        int tot = MTOT * 3 * HH * (DD / 2);   // 6291456
        rope_scatter_kernel<<<(tot + 255) / 256, 256>>>();
    }

    // 3) causal flash attention
    {
        dim3 grid(TT / AT_BQ, BB * HH);    // (16, 32)
        attn_kernel<<<grid, AT_THREADS>>>();
    }

    // 4) output projection + bias: [4096,1024] @ [1024,1024] + bo
    {
        dim3 grid(CC / BN, MTOT / BM);     // (8, 32)
        oproj_gemm_kernel<<<grid, 256>>>(Wo, bo, out);
    }
}